// round 11
// baseline (speedup 1.0000x reference)
#include <cuda_runtime.h>

// ---------------------------------------------------------------------------
// GCN: 3x (GEMM -> GCN-normalized aggregate w/ self loops -> BN(eval)+ReLU)
//      -> global mean+max pool per graph -> 2-layer MLP head.
// R10 skeleton (307.6us). This round: aggregate redesigned as two half-warps
// per node processing two edges concurrently (lane&15 -> float4 feature slice,
// lane>>4 -> edge slot). 2 independent LDG.128 row streams in flight per warp,
// half the loop iterations. shfl_xor(16) merges halves. Setup/GEMM/MLP
// byte-identical to R10.
// ---------------------------------------------------------------------------

#define NN   100000
#define EE   1600000
#define GG   512
#define INF  26
#define HF   64
#define EPSV 1e-5f
#define FULL 0xffffffffu

typedef unsigned long long ull;

// Scratch (device globals; zero-initialized at load, self-cleaned per call)
__device__ float4   g_t2[(size_t)NN * 16];  // transformed features [N,64]
__device__ float4   g_h2[(size_t)NN * 16];  // layer activations    [N,64]
__device__ int      g_deg[NN];              // edge-only in-degree (reset by scan1)
__device__ float    g_dinv[NN];             // (deg+1)^{-1/2}
__device__ int      g_rowptr[NN + 1];       // CSR row pointers (by target)
__device__ int      g_cursor[NN];           // fill cursors
__device__ int      g_csr[EE];              // source node per CSR slot
__device__ int      g_bsum[128];            // scan block sums
__device__ float    g_psum[GG * HF];        // pooling: sum   (reset by mlp)
__device__ unsigned g_pmax[GG * HF];        // pooling: max   (reset by mlp)
__device__ int      g_pcnt[GG];             // pooling: count (reset by mlp)

// ---------------------------- f32x2 helpers --------------------------------

__device__ __forceinline__ ull ffma2(ull a, ull b, ull c) {
    ull d;
    asm("fma.rn.f32x2 %0, %1, %2, %3;" : "=l"(d) : "l"(a), "l"(b), "l"(c));
    return d;
}
__device__ __forceinline__ ull pack2(float x, float y) {
    ull d;
    asm("mov.b64 %0, {%1, %2};" : "=l"(d) : "f"(x), "f"(y));
    return d;
}
__device__ __forceinline__ float2 unpack2(ull v) {
    float2 r;
    asm("mov.b64 {%0, %1}, %2;" : "=f"(r.x), "=f"(r.y) : "l"(v));
    return r;
}

// --------------------------- setup kernels ---------------------------------

__global__ void deg_kernel(const int* __restrict__ ecol) {
    int base = (blockIdx.x * blockDim.x + threadIdx.x) * 4;
    if (base + 3 < EE) {
        int4 c = *(const int4*)(ecol + base);
        atomicAdd(&g_deg[c.x], 1);
        atomicAdd(&g_deg[c.y], 1);
        atomicAdd(&g_deg[c.z], 1);
        atomicAdd(&g_deg[c.w], 1);
    } else {
        for (int e = base; e < EE; e++) atomicAdd(&g_deg[ecol[e]], 1);
    }
}

__global__ void scan1_kernel() {
    __shared__ int sbuf[1024];
    int t = threadIdx.x;
    int idx = blockIdx.x * 1024 + t;
    int v = 0;
    if (idx < NN) {
        v = g_deg[idx];                         // edges only
        g_deg[idx] = 0;                         // self-clean for next call
        g_dinv[idx] = rsqrtf((float)(v + 1));   // +1 self loop
    }
    sbuf[t] = v;
    __syncthreads();
    for (int off = 1; off < 1024; off <<= 1) {
        int tmp = (t >= off) ? sbuf[t - off] : 0;
        __syncthreads();
        sbuf[t] += tmp;
        __syncthreads();
    }
    if (idx < NN) g_rowptr[idx] = sbuf[t] - v;
    if (t == 1023) g_bsum[blockIdx.x] = sbuf[1023];
}

__global__ void scan2_kernel(int nb) {
    __shared__ int sb[128];
    int t = threadIdx.x;
    int v = (t < nb) ? g_bsum[t] : 0;
    sb[t] = v;
    __syncthreads();
    for (int off = 1; off < 128; off <<= 1) {
        int tmp = (t >= off) ? sb[t - off] : 0;
        __syncthreads();
        sb[t] += tmp;
        __syncthreads();
    }
    if (t < nb) g_bsum[t] = sb[t] - v;
}

__global__ void scan3_kernel() {
    int idx = blockIdx.x * blockDim.x + threadIdx.x;
    if (idx < NN) {
        int rp = g_rowptr[idx] + g_bsum[idx >> 10];
        g_rowptr[idx] = rp;
        g_cursor[idx] = rp;
    }
    if (idx == 0) g_rowptr[NN] = EE;
}

__global__ void csr_kernel(const int* __restrict__ erow, const int* __restrict__ ecol) {
    int base = (blockIdx.x * blockDim.x + threadIdx.x) * 4;
    if (base + 3 < EE) {
        int4 r = *(const int4*)(erow + base);
        int4 c = *(const int4*)(ecol + base);
        g_csr[atomicAdd(&g_cursor[c.x], 1)] = r.x;
        g_csr[atomicAdd(&g_cursor[c.y], 1)] = r.y;
        g_csr[atomicAdd(&g_cursor[c.z], 1)] = r.z;
        g_csr[atomicAdd(&g_cursor[c.w], 1)] = r.w;
    } else {
        for (int e = base; e < EE; e++)
            g_csr[atomicAdd(&g_cursor[ecol[e]], 1)] = erow[e];
    }
}

// ------------------------------ GEMMs ---------------------------------------
// (Byte-identical to R10.) Warp-per-8-nodes, k-split FFMA2, broadcast x reads.
__global__ void gemm26_kernel(const float* __restrict__ x, const float* __restrict__ W) {
    __shared__ __align__(16) ull  Wp[14 * HF];     // 7 KB
    __shared__ __align__(16) float xsf[64 * 28];   // 7 KB
    int tid = threadIdx.x;
    for (int i = tid; i < 14 * HF; i += 256) {
        int k2 = i >> 6, c = i & 63;
        float w0 = (2 * k2     < INF) ? W[(2 * k2)     * HF + c] : 0.f;
        float w1 = (2 * k2 + 1 < INF) ? W[(2 * k2 + 1) * HF + c] : 0.f;
        Wp[i] = pack2(w0, w1);
    }
    int base = blockIdx.x * 64;
    int cnt = min(64, NN - base);
    for (int i = tid; i < cnt * 28; i += 256) {
        int row = i / 28, col = i - row * 28;
        xsf[i] = (col < INF) ? __ldg(&x[(size_t)(base + row) * INF + col]) : 0.f;
    }
    __syncthreads();

    int lane = tid & 31;
    int n0 = (tid >> 5) * 8;
    if (n0 >= cnt) return;
    const longlong2* X4 = (const longlong2*)xsf;

    ull a0[8], a1[8];
#pragma unroll
    for (int n = 0; n < 8; n++) { a0[n] = 0ull; a1[n] = 0ull; }
#pragma unroll
    for (int k4 = 0; k4 < 7; k4++) {
        ull w00 = Wp[(2 * k4) * HF + lane];
        ull w01 = Wp[(2 * k4) * HF + 32 + lane];
        ull w10 = Wp[(2 * k4 + 1) * HF + lane];
        ull w11 = Wp[(2 * k4 + 1) * HF + 32 + lane];
#pragma unroll
        for (int n = 0; n < 8; n++) {
            longlong2 xq = X4[(n0 + n) * 7 + k4];
            a0[n] = ffma2((ull)xq.x, w00, a0[n]);
            a1[n] = ffma2((ull)xq.x, w01, a1[n]);
            a0[n] = ffma2((ull)xq.y, w10, a0[n]);
            a1[n] = ffma2((ull)xq.y, w11, a1[n]);
        }
    }
    float* dst = (float*)g_t2;
#pragma unroll
    for (int n = 0; n < 8; n++) {
        int node = base + n0 + n;
        if (node < NN) {
            float2 v0 = unpack2(a0[n]);
            float2 v1 = unpack2(a1[n]);
            dst[(size_t)node * HF + lane]      = v0.x + v0.y;
            dst[(size_t)node * HF + lane + 32] = v1.x + v1.y;
        }
    }
}

__global__ void gemm64_kernel(const float* __restrict__ W) {
    __shared__ __align__(16) ull Wp[32 * HF];      // 16 KB
    __shared__ __align__(16) ull xs2[64 * 32];     // 16 KB
    int tid = threadIdx.x;
    for (int i = tid; i < 32 * HF; i += 256) {
        int k2 = i >> 6, c = i & 63;
        Wp[i] = pack2(W[(2 * k2) * HF + c], W[(2 * k2 + 1) * HF + c]);
    }
    int base = blockIdx.x * 64;
    int cnt = min(64, NN - base);
    const ull* src = (const ull*)(g_h2 + (size_t)base * 16);
    for (int i = tid; i < cnt * 32; i += 256) xs2[i] = src[i];
    __syncthreads();

    int lane = tid & 31;
    int n0 = (tid >> 5) * 8;
    if (n0 >= cnt) return;
    const longlong2* X4 = (const longlong2*)xs2;

    ull a0[8], a1[8];
#pragma unroll
    for (int n = 0; n < 8; n++) { a0[n] = 0ull; a1[n] = 0ull; }
#pragma unroll
    for (int k4 = 0; k4 < 16; k4++) {
        ull w00 = Wp[(2 * k4) * HF + lane];
        ull w01 = Wp[(2 * k4) * HF + 32 + lane];
        ull w10 = Wp[(2 * k4 + 1) * HF + lane];
        ull w11 = Wp[(2 * k4 + 1) * HF + 32 + lane];
#pragma unroll
        for (int n = 0; n < 8; n++) {
            longlong2 xq = X4[(n0 + n) * 16 + k4];
            a0[n] = ffma2((ull)xq.x, w00, a0[n]);
            a1[n] = ffma2((ull)xq.x, w01, a1[n]);
            a0[n] = ffma2((ull)xq.y, w10, a0[n]);
            a1[n] = ffma2((ull)xq.y, w11, a1[n]);
        }
    }
    float* dst = (float*)g_t2;
#pragma unroll
    for (int n = 0; n < 8; n++) {
        int node = base + n0 + n;
        if (node < NN) {
            float2 v0 = unpack2(a0[n]);
            float2 v1 = unpack2(a1[n]);
            dst[(size_t)node * HF + lane]      = v0.x + v0.y;
            dst[(size_t)node * HF + lane + 32] = v1.x + v1.y;
        }
    }
}

// --------------------------- aggregate --------------------------------------
// Warp per target node; TWO half-warps process two edges concurrently.
// half = lane>>4 selects edge e+half (stride 2); fl = lane&15 owns features
// 4*fl..4*fl+3 (one LDG.128 covers a full 256B row per edge). shfl_xor(16)
// merges the two halves; half 0 stores + pools.
__global__ void agg_kernel(const float* __restrict__ bias,
                           const float* __restrict__ bng, const float* __restrict__ bnb,
                           const float* __restrict__ bnm, const float* __restrict__ bnv,
                           int layer, int do_pool, const int* __restrict__ batch) {
    int lane = threadIdx.x & 31;
    int half = lane >> 4;
    int fl   = lane & 15;
    int warp = (blockIdx.x * blockDim.x + threadIdx.x) >> 5;
    int nw   = (gridDim.x * blockDim.x) >> 5;
    int o = layer * HF;
    int c0 = 4 * fl;
    float sc0 = bng[o + c0]     * rsqrtf(bnv[o + c0]     + EPSV);
    float sc1 = bng[o + c0 + 1] * rsqrtf(bnv[o + c0 + 1] + EPSV);
    float sc2 = bng[o + c0 + 2] * rsqrtf(bnv[o + c0 + 2] + EPSV);
    float sc3 = bng[o + c0 + 3] * rsqrtf(bnv[o + c0 + 3] + EPSV);
    float sh0 = (bias[c0]     - bnm[o + c0])     * sc0 + bnb[o + c0];
    float sh1 = (bias[c0 + 1] - bnm[o + c0 + 1]) * sc1 + bnb[o + c0 + 1];
    float sh2 = (bias[c0 + 2] - bnm[o + c0 + 2]) * sc2 + bnb[o + c0 + 2];
    float sh3 = (bias[c0 + 3] - bnm[o + c0 + 3]) * sc3 + bnb[o + c0 + 3];

    const float4* T = g_t2;
    for (int i = warp; i < NN; i += nw) {
        float di = __ldg(&g_dinv[i]);
        int e   = __ldg(&g_rowptr[i]);
        int end = __ldg(&g_rowptr[i + 1]);
        // self-loop term counted once (half 0 only)
        ull acc0, acc1;
        {
            float4 t = __ldg(&T[(size_t)i * 16 + fl]);
            float w = half ? 0.f : di * di;
            acc0 = pack2(w * t.x, w * t.y);
            acc1 = pack2(w * t.z, w * t.w);
        }
        int idx = e + half;
        int s = 0; float w = 0.f;
        if (idx < end) {
            s = __ldg(&g_csr[idx]);
            w = __ldg(&g_dinv[s]) * di;
        }
        while (idx < end) {
            float4 r = __ldg(&T[(size_t)s * 16 + fl]);
            int nidx = idx + 2;
            int ns = 0; float nw2 = 0.f;
            if (nidx < end) {                       // prefetch next edge pair
                ns = __ldg(&g_csr[nidx]);
                nw2 = __ldg(&g_dinv[ns]) * di;
            }
            ull wp = pack2(w, w);
            acc0 = ffma2(wp, pack2(r.x, r.y), acc0);
            acc1 = ffma2(wp, pack2(r.z, r.w), acc1);
            idx = nidx; s = ns; w = nw2;
        }
        // merge the two half-warps
        float2 v0 = unpack2(acc0);
        float2 v1 = unpack2(acc1);
        v0.x += __shfl_xor_sync(FULL, v0.x, 16);
        v0.y += __shfl_xor_sync(FULL, v0.y, 16);
        v1.x += __shfl_xor_sync(FULL, v1.x, 16);
        v1.y += __shfl_xor_sync(FULL, v1.y, 16);
        // fused bias + BN(eval) + ReLU
        float o0 = fmaxf(fmaf(v0.x, sc0, sh0), 0.f);
        float o1 = fmaxf(fmaf(v0.y, sc1, sh1), 0.f);
        float o2 = fmaxf(fmaf(v1.x, sc2, sh2), 0.f);
        float o3 = fmaxf(fmaf(v1.y, sc3, sh3), 0.f);
        if (half == 0) {
            g_h2[(size_t)i * 16 + fl] = make_float4(o0, o1, o2, o3);
            if (do_pool) {
                int g = __ldg(&batch[i]);
                atomicAdd(&g_psum[g * HF + c0],     o0);
                atomicAdd(&g_psum[g * HF + c0 + 1], o1);
                atomicAdd(&g_psum[g * HF + c0 + 2], o2);
                atomicAdd(&g_psum[g * HF + c0 + 3], o3);
                atomicMax(&g_pmax[g * HF + c0],     __float_as_uint(o0));
                atomicMax(&g_pmax[g * HF + c0 + 1], __float_as_uint(o1));
                atomicMax(&g_pmax[g * HF + c0 + 2], __float_as_uint(o2));
                atomicMax(&g_pmax[g * HF + c0 + 3], __float_as_uint(o3));
                if (lane == 0) atomicAdd(&g_pcnt[g], 1);
            }
        }
    }
}

// ------------------------------ head -----------------------------------------
// (Byte-identical to R10.)
__global__ void mlp_kernel(const float* __restrict__ Wc1, const float* __restrict__ bc1,
                           const float* __restrict__ Wc2, const float* __restrict__ bc2,
                           float* __restrict__ out) {
    int lane = threadIdx.x & 31;
    int g = (blockIdx.x * blockDim.x + threadIdx.x) >> 5;
    if (g >= GG) return;
    float inv = 1.0f / fmaxf((float)g_pcnt[g], 1.0f);
    float p0 = g_psum[g * HF + lane]      * inv;
    float p1 = g_psum[g * HF + lane + 32] * inv;
    float p2 = __uint_as_float(g_pmax[g * HF + lane]);
    float p3 = __uint_as_float(g_pmax[g * HF + lane + 32]);
    g_psum[g * HF + lane] = 0.f;  g_psum[g * HF + lane + 32] = 0.f;
    g_pmax[g * HF + lane] = 0u;   g_pmax[g * HF + lane + 32] = 0u;
    if (lane == 0) g_pcnt[g] = 0;

    float h0 = bc1[lane], h1 = bc1[lane + 32];
#pragma unroll
    for (int k = 0; k < 32; k++) {
        float v0 = __shfl_sync(FULL, p0, k);
        float v1 = __shfl_sync(FULL, p1, k);
        float v2 = __shfl_sync(FULL, p2, k);
        float v3 = __shfl_sync(FULL, p3, k);
        h0 = fmaf(v0, Wc1[k * HF + lane], h0);
        h0 = fmaf(v1, Wc1[(k + 32) * HF + lane], h0);
        h0 = fmaf(v2, Wc1[(k + 64) * HF + lane], h0);
        h0 = fmaf(v3, Wc1[(k + 96) * HF + lane], h0);
        h1 = fmaf(v0, Wc1[k * HF + lane + 32], h1);
        h1 = fmaf(v1, Wc1[(k + 32) * HF + lane + 32], h1);
        h1 = fmaf(v2, Wc1[(k + 64) * HF + lane + 32], h1);
        h1 = fmaf(v3, Wc1[(k + 96) * HF + lane + 32], h1);
    }
    h0 = fmaxf(h0, 0.f);
    h1 = fmaxf(h1, 0.f);
    float o0 = h0 * Wc2[lane * 2 + 0] + h1 * Wc2[(lane + 32) * 2 + 0];
    float o1 = h0 * Wc2[lane * 2 + 1] + h1 * Wc2[(lane + 32) * 2 + 1];
#pragma unroll
    for (int off = 16; off; off >>= 1) {
        o0 += __shfl_down_sync(FULL, o0, off);
        o1 += __shfl_down_sync(FULL, o1, off);
    }
    if (lane == 0) {
        out[g * 2 + 0] = o0 + bc2[0];
        out[g * 2 + 1] = o1 + bc2[1];
    }
}

// ------------------------------ launch ---------------------------------------

extern "C" void kernel_launch(void* const* d_in, const int* in_sizes, int n_in,
                              void* d_out, int out_size) {
    const float* x    = (const float*)d_in[0];
    const int*   erow = (const int*)d_in[1];
    const int*   ecol = (const int*)d_in[2];
    const int*   batch= (const int*)d_in[3];
    const float* W0   = (const float*)d_in[4];
    const float* b0   = (const float*)d_in[5];
    const float* W1   = (const float*)d_in[6];
    const float* b1   = (const float*)d_in[7];
    const float* W2   = (const float*)d_in[8];
    const float* b2   = (const float*)d_in[9];
    const float* bng  = (const float*)d_in[10];
    const float* bnb  = (const float*)d_in[11];
    const float* bnm  = (const float*)d_in[12];
    const float* bnv  = (const float*)d_in[13];
    const float* Wc1  = (const float*)d_in[14];
    const float* bc1  = (const float*)d_in[15];
    const float* Wc2  = (const float*)d_in[16];
    const float* bc2  = (const float*)d_in[17];
    float* out = (float*)d_out;

    const int GB = 2048, BT = 256;
    const int GEMM_BLOCKS = (NN + 63) / 64;

    deg_kernel<<<(EE / 4 + 255) / 256, 256>>>(ecol);
    scan1_kernel<<<(NN + 1023) / 1024, 1024>>>();
    scan2_kernel<<<1, 128>>>((NN + 1023) / 1024);
    gemm26_kernel<<<GEMM_BLOCKS, 256>>>(x, W0);
    scan3_kernel<<<(NN + 255) / 256, 256>>>();
    csr_kernel<<<(EE / 4 + 255) / 256, 256>>>(erow, ecol);

    agg_kernel<<<GB, BT>>>(b0, bng, bnb, bnm, bnv, 0, 0, batch);
    gemm64_kernel<<<GEMM_BLOCKS, 256>>>(W1);
    agg_kernel<<<GB, BT>>>(b1, bng, bnb, bnm, bnv, 1, 0, batch);
    gemm64_kernel<<<GEMM_BLOCKS, 256>>>(W2);
    agg_kernel<<<GB, BT>>>(b2, bng, bnb, bnm, bnv, 2, 1, batch);
    mlp_kernel<<<(GG * 32 + 255) / 256, 256>>>(Wc1, bc1, Wc2, bc2, out);
}

// round 12
// speedup vs baseline: 1.0963x; 1.0963x over previous
#include <cuda_runtime.h>
#include <cuda_fp16.h>

// ---------------------------------------------------------------------------
// GCN: 3x (GEMM -> GCN-normalized aggregate w/ self loops -> BN(eval)+ReLU)
//      -> global mean+max pool per graph -> 2-layer MLP head.
// Best skeleton (307.6us, R9 aggregate shape). This round:
//  - t gather buffer in fp16 (half2): 128B rows = 1 line/edge, fp32 accumulate
//  - aggregate: 2-deep software pipeline, two independent row streams
//  - GEMMs: pair-column output mapping (lane owns 2l,2l+1), LDS.128 W reads,
//    half2 epilogue store. Setup/MLP unchanged.
// ---------------------------------------------------------------------------

#define NN   100000
#define EE   1600000
#define GG   512
#define INF  26
#define HF   64
#define EPSV 1e-5f
#define FULL 0xffffffffu

typedef unsigned long long ull;

// Scratch (device globals; zero-initialized at load, self-cleaned per call)
__device__ __half2  g_th[(size_t)NN * 32];  // transformed features, fp16 [N,64]
__device__ float2   g_h2[(size_t)NN * 32];  // layer activations, fp32 [N,64]
__device__ int      g_deg[NN];              // edge-only in-degree (reset by scan1)
__device__ float    g_dinv[NN];             // (deg+1)^{-1/2}
__device__ int      g_rowptr[NN + 1];       // CSR row pointers (by target)
__device__ int      g_cursor[NN];           // fill cursors
__device__ int      g_csr[EE];              // source node per CSR slot
__device__ int      g_bsum[128];            // scan block sums
__device__ float    g_psum[GG * HF];        // pooling: sum   (reset by mlp)
__device__ unsigned g_pmax[GG * HF];        // pooling: max   (reset by mlp)
__device__ int      g_pcnt[GG];             // pooling: count (reset by mlp)

// ---------------------------- f32x2 helpers --------------------------------

__device__ __forceinline__ ull ffma2(ull a, ull b, ull c) {
    ull d;
    asm("fma.rn.f32x2 %0, %1, %2, %3;" : "=l"(d) : "l"(a), "l"(b), "l"(c));
    return d;
}
__device__ __forceinline__ ull addf2(ull a, ull b) {
    ull d;
    asm("add.rn.f32x2 %0, %1, %2;" : "=l"(d) : "l"(a), "l"(b));
    return d;
}
__device__ __forceinline__ ull pack2(float x, float y) {
    ull d;
    asm("mov.b64 %0, {%1, %2};" : "=l"(d) : "f"(x), "f"(y));
    return d;
}
__device__ __forceinline__ float2 unpack2(ull v) {
    float2 r;
    asm("mov.b64 {%0, %1}, %2;" : "=f"(r.x), "=f"(r.y) : "l"(v));
    return r;
}

// --------------------------- setup kernels ---------------------------------

__global__ void deg_kernel(const int* __restrict__ ecol) {
    int base = (blockIdx.x * blockDim.x + threadIdx.x) * 4;
    if (base + 3 < EE) {
        int4 c = *(const int4*)(ecol + base);
        atomicAdd(&g_deg[c.x], 1);
        atomicAdd(&g_deg[c.y], 1);
        atomicAdd(&g_deg[c.z], 1);
        atomicAdd(&g_deg[c.w], 1);
    } else {
        for (int e = base; e < EE; e++) atomicAdd(&g_deg[ecol[e]], 1);
    }
}

__global__ void scan1_kernel() {
    __shared__ int sbuf[1024];
    int t = threadIdx.x;
    int idx = blockIdx.x * 1024 + t;
    int v = 0;
    if (idx < NN) {
        v = g_deg[idx];                         // edges only
        g_deg[idx] = 0;                         // self-clean for next call
        g_dinv[idx] = rsqrtf((float)(v + 1));   // +1 self loop
    }
    sbuf[t] = v;
    __syncthreads();
    for (int off = 1; off < 1024; off <<= 1) {
        int tmp = (t >= off) ? sbuf[t - off] : 0;
        __syncthreads();
        sbuf[t] += tmp;
        __syncthreads();
    }
    if (idx < NN) g_rowptr[idx] = sbuf[t] - v;
    if (t == 1023) g_bsum[blockIdx.x] = sbuf[1023];
}

__global__ void scan2_kernel(int nb) {
    __shared__ int sb[128];
    int t = threadIdx.x;
    int v = (t < nb) ? g_bsum[t] : 0;
    sb[t] = v;
    __syncthreads();
    for (int off = 1; off < 128; off <<= 1) {
        int tmp = (t >= off) ? sb[t - off] : 0;
        __syncthreads();
        sb[t] += tmp;
        __syncthreads();
    }
    if (t < nb) g_bsum[t] = sb[t] - v;
}

__global__ void scan3_kernel() {
    int idx = blockIdx.x * blockDim.x + threadIdx.x;
    if (idx < NN) {
        int rp = g_rowptr[idx] + g_bsum[idx >> 10];
        g_rowptr[idx] = rp;
        g_cursor[idx] = rp;
    }
    if (idx == 0) g_rowptr[NN] = EE;
}

__global__ void csr_kernel(const int* __restrict__ erow, const int* __restrict__ ecol) {
    int base = (blockIdx.x * blockDim.x + threadIdx.x) * 4;
    if (base + 3 < EE) {
        int4 r = *(const int4*)(erow + base);
        int4 c = *(const int4*)(ecol + base);
        g_csr[atomicAdd(&g_cursor[c.x], 1)] = r.x;
        g_csr[atomicAdd(&g_cursor[c.y], 1)] = r.y;
        g_csr[atomicAdd(&g_cursor[c.z], 1)] = r.z;
        g_csr[atomicAdd(&g_cursor[c.w], 1)] = r.w;
    } else {
        for (int e = base; e < EE; e++)
            g_csr[atomicAdd(&g_cursor[ecol[e]], 1)] = erow[e];
    }
}

// ------------------------------ GEMMs ---------------------------------------
// Warp-per-8-nodes, k-split FFMA2. Lane owns OUTPUT COLUMNS (2*lane, 2*lane+1):
// one LDS.128 fetches both W k-pairs; epilogue packs straight to half2.
__global__ void gemm26_kernel(const float* __restrict__ x, const float* __restrict__ W) {
    __shared__ __align__(16) ull  Wp[14 * HF];     // Wp[k2*64+c]=(W[2k2][c],W[2k2+1][c])
    __shared__ __align__(16) float xsf[64 * 28];
    int tid = threadIdx.x;
    for (int i = tid; i < 14 * HF; i += 256) {
        int k2 = i >> 6, c = i & 63;
        float w0 = (2 * k2     < INF) ? W[(2 * k2)     * HF + c] : 0.f;
        float w1 = (2 * k2 + 1 < INF) ? W[(2 * k2 + 1) * HF + c] : 0.f;
        Wp[i] = pack2(w0, w1);
    }
    int base = blockIdx.x * 64;
    int cnt = min(64, NN - base);
    for (int i = tid; i < cnt * 28; i += 256) {
        int row = i / 28, col = i - row * 28;
        xsf[i] = (col < INF) ? __ldg(&x[(size_t)(base + row) * INF + col]) : 0.f;
    }
    __syncthreads();

    int lane = tid & 31;
    int n0 = (tid >> 5) * 8;
    if (n0 >= cnt) return;
    const longlong2* X4 = (const longlong2*)xsf;
    const longlong2* Wq = (const longlong2*)Wp;   // Wq[k2*32+l] = cols (2l, 2l+1)

    ull a0[8], a1[8];
#pragma unroll
    for (int n = 0; n < 8; n++) { a0[n] = 0ull; a1[n] = 0ull; }
#pragma unroll
    for (int k4 = 0; k4 < 7; k4++) {
        longlong2 wq0 = Wq[(2 * k4) * 32 + lane];       // k in {4k4, 4k4+1}
        longlong2 wq1 = Wq[(2 * k4 + 1) * 32 + lane];   // k in {4k4+2, 4k4+3}
#pragma unroll
        for (int n = 0; n < 8; n++) {
            longlong2 xq = X4[(n0 + n) * 7 + k4];
            a0[n] = ffma2((ull)xq.x, (ull)wq0.x, a0[n]);
            a1[n] = ffma2((ull)xq.x, (ull)wq0.y, a1[n]);
            a0[n] = ffma2((ull)xq.y, (ull)wq1.x, a0[n]);
            a1[n] = ffma2((ull)xq.y, (ull)wq1.y, a1[n]);
        }
    }
#pragma unroll
    for (int n = 0; n < 8; n++) {
        int node = base + n0 + n;
        if (node < NN) {
            float2 v0 = unpack2(a0[n]);
            float2 v1 = unpack2(a1[n]);
            g_th[(size_t)node * 32 + lane] = __floats2half2_rn(v0.x + v0.y, v1.x + v1.y);
        }
    }
}

__global__ void gemm64_kernel(const float* __restrict__ W) {
    __shared__ __align__(16) ull Wp[32 * HF];
    __shared__ __align__(16) ull xs2[64 * 32];
    int tid = threadIdx.x;
    for (int i = tid; i < 32 * HF; i += 256) {
        int k2 = i >> 6, c = i & 63;
        Wp[i] = pack2(W[(2 * k2) * HF + c], W[(2 * k2 + 1) * HF + c]);
    }
    int base = blockIdx.x * 64;
    int cnt = min(64, NN - base);
    const ull* src = (const ull*)(g_h2 + (size_t)base * 32);
    for (int i = tid; i < cnt * 32; i += 256) xs2[i] = src[i];
    __syncthreads();

    int lane = tid & 31;
    int n0 = (tid >> 5) * 8;
    if (n0 >= cnt) return;
    const longlong2* X4 = (const longlong2*)xs2;
    const longlong2* Wq = (const longlong2*)Wp;

    ull a0[8], a1[8];
#pragma unroll
    for (int n = 0; n < 8; n++) { a0[n] = 0ull; a1[n] = 0ull; }
#pragma unroll
    for (int k4 = 0; k4 < 16; k4++) {
        longlong2 wq0 = Wq[(2 * k4) * 32 + lane];
        longlong2 wq1 = Wq[(2 * k4 + 1) * 32 + lane];
#pragma unroll
        for (int n = 0; n < 8; n++) {
            longlong2 xq = X4[(n0 + n) * 16 + k4];
            a0[n] = ffma2((ull)xq.x, (ull)wq0.x, a0[n]);
            a1[n] = ffma2((ull)xq.x, (ull)wq0.y, a1[n]);
            a0[n] = ffma2((ull)xq.y, (ull)wq1.x, a0[n]);
            a1[n] = ffma2((ull)xq.y, (ull)wq1.y, a1[n]);
        }
    }
#pragma unroll
    for (int n = 0; n < 8; n++) {
        int node = base + n0 + n;
        if (node < NN) {
            float2 v0 = unpack2(a0[n]);
            float2 v1 = unpack2(a1[n]);
            g_th[(size_t)node * 32 + lane] = __floats2half2_rn(v0.x + v0.y, v1.x + v1.y);
        }
    }
}

// --------------------------- aggregate --------------------------------------
// Warp per target node (strided), lane owns features (2l, 2l+1) as half2.
// 2-deep pipeline: two independent (w, row) streams in registers; paired
// prefetch keeps 2 LDG.32 row loads in flight. fp32 accumulation (f32x2).
__global__ void agg_kernel(const float* __restrict__ bias,
                           const float* __restrict__ bng, const float* __restrict__ bnb,
                           const float* __restrict__ bnm, const float* __restrict__ bnv,
                           int layer, int do_pool, const int* __restrict__ batch) {
    int lane = threadIdx.x & 31;
    int warp = (blockIdx.x * blockDim.x + threadIdx.x) >> 5;
    int nw   = (gridDim.x * blockDim.x) >> 5;
    int c0 = 2 * lane, c1 = 2 * lane + 1;
    int o = layer * HF;
    float sc0 = bng[o + c0] * rsqrtf(bnv[o + c0] + EPSV);
    float sc1 = bng[o + c1] * rsqrtf(bnv[o + c1] + EPSV);
    float sh0 = (bias[c0] - bnm[o + c0]) * sc0 + bnb[o + c0];
    float sh1 = (bias[c1] - bnm[o + c1]) * sc1 + bnb[o + c1];

    for (int i = warp; i < NN; i += nw) {
        float di = __ldg(&g_dinv[i]);
        float di2 = di * di;
        float2 tt = __half22float2(__ldg(&g_th[(size_t)i * 32 + lane]));
        ull accA = pack2(di2 * tt.x, di2 * tt.y);
        ull accB = 0ull;
        int e   = __ldg(&g_rowptr[i]);
        int end = __ldg(&g_rowptr[i + 1]);
        int m = end - e;
        if (m == 1) {
            int s = __ldg(&g_csr[e]);
            float w = __ldg(&g_dinv[s]) * di;
            float2 f = __half22float2(__ldg(&g_th[(size_t)s * 32 + lane]));
            accA = ffma2(pack2(w, w), pack2(f.x, f.y), accA);
        } else if (m >= 2) {
            int sA = __ldg(&g_csr[e]);
            int sB = __ldg(&g_csr[e + 1]);
            float wA = __ldg(&g_dinv[sA]) * di;
            float wB = __ldg(&g_dinv[sB]) * di;
            __half2 rA = __ldg(&g_th[(size_t)sA * 32 + lane]);
            __half2 rB = __ldg(&g_th[(size_t)sB * 32 + lane]);
            int k = e + 2;
            while (k + 1 < end) {
                int sC = __ldg(&g_csr[k]);
                int sD = __ldg(&g_csr[k + 1]);
                float wC = __ldg(&g_dinv[sC]) * di;
                float wD = __ldg(&g_dinv[sD]) * di;
                __half2 rC = __ldg(&g_th[(size_t)sC * 32 + lane]);
                __half2 rD = __ldg(&g_th[(size_t)sD * 32 + lane]);
                float2 fA = __half22float2(rA);
                float2 fB = __half22float2(rB);
                accA = ffma2(pack2(wA, wA), pack2(fA.x, fA.y), accA);
                accB = ffma2(pack2(wB, wB), pack2(fB.x, fB.y), accB);
                wA = wC; rA = rC;
                wB = wD; rB = rD;
                k += 2;
            }
            if (k < end) {                       // one more to prefetch
                int sC = __ldg(&g_csr[k]);
                float wC = __ldg(&g_dinv[sC]) * di;
                __half2 rC = __ldg(&g_th[(size_t)sC * 32 + lane]);
                float2 fA = __half22float2(rA);
                float2 fB = __half22float2(rB);
                accA = ffma2(pack2(wA, wA), pack2(fA.x, fA.y), accA);
                accB = ffma2(pack2(wB, wB), pack2(fB.x, fB.y), accB);
                float2 fC = __half22float2(rC);
                accA = ffma2(pack2(wC, wC), pack2(fC.x, fC.y), accA);
            } else {
                float2 fA = __half22float2(rA);
                float2 fB = __half22float2(rB);
                accA = ffma2(pack2(wA, wA), pack2(fA.x, fA.y), accA);
                accB = ffma2(pack2(wB, wB), pack2(fB.x, fB.y), accB);
            }
        }
        float2 av = unpack2(addf2(accA, accB));
        float o0 = fmaxf(fmaf(av.x, sc0, sh0), 0.f);
        float o1 = fmaxf(fmaf(av.y, sc1, sh1), 0.f);
        g_h2[(size_t)i * 32 + lane] = make_float2(o0, o1);
        if (do_pool) {
            int g = __ldg(&batch[i]);
            atomicAdd(&g_psum[g * HF + c0], o0);
            atomicAdd(&g_psum[g * HF + c1], o1);
            atomicMax(&g_pmax[g * HF + c0], __float_as_uint(o0));
            atomicMax(&g_pmax[g * HF + c1], __float_as_uint(o1));
            if (lane == 0) atomicAdd(&g_pcnt[g], 1);
        }
    }
}

// ------------------------------ head -----------------------------------------
// (Unchanged; pooling layout [g*64 + c], c matches agg's c0=2*lane mapping.)
__global__ void mlp_kernel(const float* __restrict__ Wc1, const float* __restrict__ bc1,
                           const float* __restrict__ Wc2, const float* __restrict__ bc2,
                           float* __restrict__ out) {
    int lane = threadIdx.x & 31;
    int g = (blockIdx.x * blockDim.x + threadIdx.x) >> 5;
    if (g >= GG) return;
    float inv = 1.0f / fmaxf((float)g_pcnt[g], 1.0f);
    float p0 = g_psum[g * HF + lane]      * inv;
    float p1 = g_psum[g * HF + lane + 32] * inv;
    float p2 = __uint_as_float(g_pmax[g * HF + lane]);
    float p3 = __uint_as_float(g_pmax[g * HF + lane + 32]);
    g_psum[g * HF + lane] = 0.f;  g_psum[g * HF + lane + 32] = 0.f;
    g_pmax[g * HF + lane] = 0u;   g_pmax[g * HF + lane + 32] = 0u;
    if (lane == 0) g_pcnt[g] = 0;

    float h0 = bc1[lane], h1 = bc1[lane + 32];
#pragma unroll
    for (int k = 0; k < 32; k++) {
        float v0 = __shfl_sync(FULL, p0, k);
        float v1 = __shfl_sync(FULL, p1, k);
        float v2 = __shfl_sync(FULL, p2, k);
        float v3 = __shfl_sync(FULL, p3, k);
        h0 = fmaf(v0, Wc1[k * HF + lane], h0);
        h0 = fmaf(v1, Wc1[(k + 32) * HF + lane], h0);
        h0 = fmaf(v2, Wc1[(k + 64) * HF + lane], h0);
        h0 = fmaf(v3, Wc1[(k + 96) * HF + lane], h0);
        h1 = fmaf(v0, Wc1[k * HF + lane + 32], h1);
        h1 = fmaf(v1, Wc1[(k + 32) * HF + lane + 32], h1);
        h1 = fmaf(v2, Wc1[(k + 64) * HF + lane + 32], h1);
        h1 = fmaf(v3, Wc1[(k + 96) * HF + lane + 32], h1);
    }
    h0 = fmaxf(h0, 0.f);
    h1 = fmaxf(h1, 0.f);
    float o0 = h0 * Wc2[lane * 2 + 0] + h1 * Wc2[(lane + 32) * 2 + 0];
    float o1 = h0 * Wc2[lane * 2 + 1] + h1 * Wc2[(lane + 32) * 2 + 1];
#pragma unroll
    for (int off = 16; off; off >>= 1) {
        o0 += __shfl_down_sync(FULL, o0, off);
        o1 += __shfl_down_sync(FULL, o1, off);
    }
    if (lane == 0) {
        out[g * 2 + 0] = o0 + bc2[0];
        out[g * 2 + 1] = o1 + bc2[1];
    }
}

// ------------------------------ launch ---------------------------------------

extern "C" void kernel_launch(void* const* d_in, const int* in_sizes, int n_in,
                              void* d_out, int out_size) {
    const float* x    = (const float*)d_in[0];
    const int*   erow = (const int*)d_in[1];
    const int*   ecol = (const int*)d_in[2];
    const int*   batch= (const int*)d_in[3];
    const float* W0   = (const float*)d_in[4];
    const float* b0   = (const float*)d_in[5];
    const float* W1   = (const float*)d_in[6];
    const float* b1   = (const float*)d_in[7];
    const float* W2   = (const float*)d_in[8];
    const float* b2   = (const float*)d_in[9];
    const float* bng  = (const float*)d_in[10];
    const float* bnb  = (const float*)d_in[11];
    const float* bnm  = (const float*)d_in[12];
    const float* bnv  = (const float*)d_in[13];
    const float* Wc1  = (const float*)d_in[14];
    const float* bc1  = (const float*)d_in[15];
    const float* Wc2  = (const float*)d_in[16];
    const float* bc2  = (const float*)d_in[17];
    float* out = (float*)d_out;

    const int GB = 2048, BT = 256;
    const int GEMM_BLOCKS = (NN + 63) / 64;

    deg_kernel<<<(EE / 4 + 255) / 256, 256>>>(ecol);
    scan1_kernel<<<(NN + 1023) / 1024, 1024>>>();
    scan2_kernel<<<1, 128>>>((NN + 1023) / 1024);
    gemm26_kernel<<<GEMM_BLOCKS, 256>>>(x, W0);
    scan3_kernel<<<(NN + 255) / 256, 256>>>();
    csr_kernel<<<(EE / 4 + 255) / 256, 256>>>(erow, ecol);

    agg_kernel<<<GB, BT>>>(b0, bng, bnb, bnm, bnv, 0, 0, batch);
    gemm64_kernel<<<GEMM_BLOCKS, 256>>>(W1);
    agg_kernel<<<GB, BT>>>(b1, bng, bnb, bnm, bnv, 1, 0, batch);
    gemm64_kernel<<<GEMM_BLOCKS, 256>>>(W2);
    agg_kernel<<<GB, BT>>>(b2, bng, bnb, bnm, bnv, 2, 1, batch);
    mlp_kernel<<<(GG * 32 + 255) / 256, 256>>>(Wc1, bc1, Wc2, bc2, out);
}

// round 13
// speedup vs baseline: 1.2674x; 1.1560x over previous
#include <cuda_runtime.h>
#include <cuda_fp16.h>

// ---------------------------------------------------------------------------
// GCN: 3x (GEMM -> GCN-normalized aggregate w/ self loops -> BN(eval)+ReLU)
//      -> global mean+max pool per graph -> 2-layer MLP head.
// R11 skeleton (298.9us). This round: pre-scaled gather rows t'[s]=dinv_s*t_s
// (scaling folded into GEMM epilogue) => aggregate is a pure unweighted sum:
// per edge just csr[e] + one fp16 row load. 4 independent row streams with
// 4-ahead prefetch; target dinv_i folds into the BN affine per node.
// ---------------------------------------------------------------------------

#define NN   100000
#define EE   1600000
#define GG   512
#define INF  26
#define HF   64
#define EPSV 1e-5f
#define FULL 0xffffffffu

typedef unsigned long long ull;

// Scratch (device globals; zero-initialized at load, self-cleaned per call)
__device__ __half2  g_th[(size_t)NN * 32];  // PRE-SCALED features dinv*t, fp16
__device__ float2   g_h2[(size_t)NN * 32];  // layer activations, fp32 [N,64]
__device__ int      g_deg[NN];              // edge-only in-degree (reset by scan1)
__device__ float    g_dinv[NN];             // (deg+1)^{-1/2}
__device__ int      g_rowptr[NN + 1];       // CSR row pointers (by target)
__device__ int      g_cursor[NN];           // fill cursors
__device__ int      g_csr[EE];              // source node per CSR slot
__device__ int      g_bsum[128];            // scan block sums
__device__ float    g_psum[GG * HF];        // pooling: sum   (reset by mlp)
__device__ unsigned g_pmax[GG * HF];        // pooling: max   (reset by mlp)
__device__ int      g_pcnt[GG];             // pooling: count (reset by mlp)

// ---------------------------- f32x2 helpers --------------------------------

__device__ __forceinline__ ull ffma2(ull a, ull b, ull c) {
    ull d;
    asm("fma.rn.f32x2 %0, %1, %2, %3;" : "=l"(d) : "l"(a), "l"(b), "l"(c));
    return d;
}
__device__ __forceinline__ ull pack2(float x, float y) {
    ull d;
    asm("mov.b64 %0, {%1, %2};" : "=l"(d) : "f"(x), "f"(y));
    return d;
}
__device__ __forceinline__ float2 unpack2(ull v) {
    float2 r;
    asm("mov.b64 {%0, %1}, %2;" : "=f"(r.x), "=f"(r.y) : "l"(v));
    return r;
}

// --------------------------- setup kernels ---------------------------------

__global__ void deg_kernel(const int* __restrict__ ecol) {
    int base = (blockIdx.x * blockDim.x + threadIdx.x) * 4;
    if (base + 3 < EE) {
        int4 c = *(const int4*)(ecol + base);
        atomicAdd(&g_deg[c.x], 1);
        atomicAdd(&g_deg[c.y], 1);
        atomicAdd(&g_deg[c.z], 1);
        atomicAdd(&g_deg[c.w], 1);
    } else {
        for (int e = base; e < EE; e++) atomicAdd(&g_deg[ecol[e]], 1);
    }
}

__global__ void scan1_kernel() {
    __shared__ int sbuf[1024];
    int t = threadIdx.x;
    int idx = blockIdx.x * 1024 + t;
    int v = 0;
    if (idx < NN) {
        v = g_deg[idx];                         // edges only
        g_deg[idx] = 0;                         // self-clean for next call
        g_dinv[idx] = rsqrtf((float)(v + 1));   // +1 self loop
    }
    sbuf[t] = v;
    __syncthreads();
    for (int off = 1; off < 1024; off <<= 1) {
        int tmp = (t >= off) ? sbuf[t - off] : 0;
        __syncthreads();
        sbuf[t] += tmp;
        __syncthreads();
    }
    if (idx < NN) g_rowptr[idx] = sbuf[t] - v;
    if (t == 1023) g_bsum[blockIdx.x] = sbuf[1023];
}

__global__ void scan2_kernel(int nb) {
    __shared__ int sb[128];
    int t = threadIdx.x;
    int v = (t < nb) ? g_bsum[t] : 0;
    sb[t] = v;
    __syncthreads();
    for (int off = 1; off < 128; off <<= 1) {
        int tmp = (t >= off) ? sb[t - off] : 0;
        __syncthreads();
        sb[t] += tmp;
        __syncthreads();
    }
    if (t < nb) g_bsum[t] = sb[t] - v;
}

__global__ void scan3_kernel() {
    int idx = blockIdx.x * blockDim.x + threadIdx.x;
    if (idx < NN) {
        int rp = g_rowptr[idx] + g_bsum[idx >> 10];
        g_rowptr[idx] = rp;
        g_cursor[idx] = rp;
    }
    if (idx == 0) g_rowptr[NN] = EE;
}

__global__ void csr_kernel(const int* __restrict__ erow, const int* __restrict__ ecol) {
    int base = (blockIdx.x * blockDim.x + threadIdx.x) * 4;
    if (base + 3 < EE) {
        int4 r = *(const int4*)(erow + base);
        int4 c = *(const int4*)(ecol + base);
        g_csr[atomicAdd(&g_cursor[c.x], 1)] = r.x;
        g_csr[atomicAdd(&g_cursor[c.y], 1)] = r.y;
        g_csr[atomicAdd(&g_cursor[c.z], 1)] = r.z;
        g_csr[atomicAdd(&g_cursor[c.w], 1)] = r.w;
    } else {
        for (int e = base; e < EE; e++)
            g_csr[atomicAdd(&g_cursor[ecol[e]], 1)] = erow[e];
    }
}

// ------------------------------ GEMMs ---------------------------------------
// Warp-per-8-nodes, k-split FFMA2, lane owns output columns (2l, 2l+1).
// Epilogue scales by dinv[node] and stores half2 (pre-scaled gather rows).
__global__ void gemm26_kernel(const float* __restrict__ x, const float* __restrict__ W) {
    __shared__ __align__(16) ull  Wp[14 * HF];
    __shared__ __align__(16) float xsf[64 * 28];
    int tid = threadIdx.x;
    for (int i = tid; i < 14 * HF; i += 256) {
        int k2 = i >> 6, c = i & 63;
        float w0 = (2 * k2     < INF) ? W[(2 * k2)     * HF + c] : 0.f;
        float w1 = (2 * k2 + 1 < INF) ? W[(2 * k2 + 1) * HF + c] : 0.f;
        Wp[i] = pack2(w0, w1);
    }
    int base = blockIdx.x * 64;
    int cnt = min(64, NN - base);
    for (int i = tid; i < cnt * 28; i += 256) {
        int row = i / 28, col = i - row * 28;
        xsf[i] = (col < INF) ? __ldg(&x[(size_t)(base + row) * INF + col]) : 0.f;
    }
    __syncthreads();

    int lane = tid & 31;
    int n0 = (tid >> 5) * 8;
    if (n0 >= cnt) return;
    const longlong2* X4 = (const longlong2*)xsf;
    const longlong2* Wq = (const longlong2*)Wp;

    ull a0[8], a1[8];
#pragma unroll
    for (int n = 0; n < 8; n++) { a0[n] = 0ull; a1[n] = 0ull; }
#pragma unroll
    for (int k4 = 0; k4 < 7; k4++) {
        longlong2 wq0 = Wq[(2 * k4) * 32 + lane];
        longlong2 wq1 = Wq[(2 * k4 + 1) * 32 + lane];
#pragma unroll
        for (int n = 0; n < 8; n++) {
            longlong2 xq = X4[(n0 + n) * 7 + k4];
            a0[n] = ffma2((ull)xq.x, (ull)wq0.x, a0[n]);
            a1[n] = ffma2((ull)xq.x, (ull)wq0.y, a1[n]);
            a0[n] = ffma2((ull)xq.y, (ull)wq1.x, a0[n]);
            a1[n] = ffma2((ull)xq.y, (ull)wq1.y, a1[n]);
        }
    }
#pragma unroll
    for (int n = 0; n < 8; n++) {
        int node = base + n0 + n;
        if (node < NN) {
            float dn = __ldg(&g_dinv[node]);
            float2 v0 = unpack2(a0[n]);
            float2 v1 = unpack2(a1[n]);
            g_th[(size_t)node * 32 + lane] =
                __floats2half2_rn(dn * (v0.x + v0.y), dn * (v1.x + v1.y));
        }
    }
}

__global__ void gemm64_kernel(const float* __restrict__ W) {
    __shared__ __align__(16) ull Wp[32 * HF];
    __shared__ __align__(16) ull xs2[64 * 32];
    int tid = threadIdx.x;
    for (int i = tid; i < 32 * HF; i += 256) {
        int k2 = i >> 6, c = i & 63;
        Wp[i] = pack2(W[(2 * k2) * HF + c], W[(2 * k2 + 1) * HF + c]);
    }
    int base = blockIdx.x * 64;
    int cnt = min(64, NN - base);
    const ull* src = (const ull*)(g_h2 + (size_t)base * 32);
    for (int i = tid; i < cnt * 32; i += 256) xs2[i] = src[i];
    __syncthreads();

    int lane = tid & 31;
    int n0 = (tid >> 5) * 8;
    if (n0 >= cnt) return;
    const longlong2* X4 = (const longlong2*)xs2;
    const longlong2* Wq = (const longlong2*)Wp;

    ull a0[8], a1[8];
#pragma unroll
    for (int n = 0; n < 8; n++) { a0[n] = 0ull; a1[n] = 0ull; }
#pragma unroll
    for (int k4 = 0; k4 < 16; k4++) {
        longlong2 wq0 = Wq[(2 * k4) * 32 + lane];
        longlong2 wq1 = Wq[(2 * k4 + 1) * 32 + lane];
#pragma unroll
        for (int n = 0; n < 8; n++) {
            longlong2 xq = X4[(n0 + n) * 16 + k4];
            a0[n] = ffma2((ull)xq.x, (ull)wq0.x, a0[n]);
            a1[n] = ffma2((ull)xq.x, (ull)wq0.y, a1[n]);
            a0[n] = ffma2((ull)xq.y, (ull)wq1.x, a0[n]);
            a1[n] = ffma2((ull)xq.y, (ull)wq1.y, a1[n]);
        }
    }
#pragma unroll
    for (int n = 0; n < 8; n++) {
        int node = base + n0 + n;
        if (node < NN) {
            float dn = __ldg(&g_dinv[node]);
            float2 v0 = unpack2(a0[n]);
            float2 v1 = unpack2(a1[n]);
            g_th[(size_t)node * 32 + lane] =
                __floats2half2_rn(dn * (v0.x + v0.y), dn * (v1.x + v1.y));
        }
    }
}

// --------------------------- aggregate --------------------------------------
// Pure unweighted gather-sum over pre-scaled fp16 rows. Warp per node, lane
// owns features (2l,2l+1). 4 independent row streams, prefetched 4 ahead.
// h_i = dinv_i * (t'[i] + sum t'[s]);  dinv_i folds into the BN affine.
__global__ void agg_kernel(const float* __restrict__ bias,
                           const float* __restrict__ bng, const float* __restrict__ bnb,
                           const float* __restrict__ bnm, const float* __restrict__ bnv,
                           int layer, int do_pool, const int* __restrict__ batch) {
    int lane = threadIdx.x & 31;
    int warp = (blockIdx.x * blockDim.x + threadIdx.x) >> 5;
    int nw   = (gridDim.x * blockDim.x) >> 5;
    int c0 = 2 * lane, c1 = 2 * lane + 1;
    int o = layer * HF;
    float sc0 = bng[o + c0] * rsqrtf(bnv[o + c0] + EPSV);
    float sc1 = bng[o + c1] * rsqrtf(bnv[o + c1] + EPSV);
    float sh0 = (bias[c0] - bnm[o + c0]) * sc0 + bnb[o + c0];
    float sh1 = (bias[c1] - bnm[o + c1]) * sc1 + bnb[o + c1];

    const __half2* T = g_th;
    for (int i = warp; i < NN; i += nw) {
        float di = __ldg(&g_dinv[i]);
        float2 accA = __half22float2(__ldg(&T[(size_t)i * 32 + lane]));  // self
        float2 accB = make_float2(0.f, 0.f);
        float2 accC = make_float2(0.f, 0.f);
        float2 accD = make_float2(0.f, 0.f);
        int e   = __ldg(&g_rowptr[i]);
        int end = __ldg(&g_rowptr[i + 1]);
        int k = e;
        if (k + 3 < end) {
            int s0 = __ldg(&g_csr[k]);
            int s1 = __ldg(&g_csr[k + 1]);
            int s2 = __ldg(&g_csr[k + 2]);
            int s3 = __ldg(&g_csr[k + 3]);
            __half2 r0 = __ldg(&T[(size_t)s0 * 32 + lane]);
            __half2 r1 = __ldg(&T[(size_t)s1 * 32 + lane]);
            __half2 r2 = __ldg(&T[(size_t)s2 * 32 + lane]);
            __half2 r3 = __ldg(&T[(size_t)s3 * 32 + lane]);
            k += 4;
            while (k + 3 < end) {
                int n0 = __ldg(&g_csr[k]);
                int n1 = __ldg(&g_csr[k + 1]);
                int n2 = __ldg(&g_csr[k + 2]);
                int n3 = __ldg(&g_csr[k + 3]);
                __half2 q0 = __ldg(&T[(size_t)n0 * 32 + lane]);
                __half2 q1 = __ldg(&T[(size_t)n1 * 32 + lane]);
                __half2 q2 = __ldg(&T[(size_t)n2 * 32 + lane]);
                __half2 q3 = __ldg(&T[(size_t)n3 * 32 + lane]);
                float2 f0 = __half22float2(r0);
                float2 f1 = __half22float2(r1);
                float2 f2 = __half22float2(r2);
                float2 f3 = __half22float2(r3);
                accA.x += f0.x; accA.y += f0.y;
                accB.x += f1.x; accB.y += f1.y;
                accC.x += f2.x; accC.y += f2.y;
                accD.x += f3.x; accD.y += f3.y;
                r0 = q0; r1 = q1; r2 = q2; r3 = q3;
                k += 4;
            }
            float2 f0 = __half22float2(r0);
            float2 f1 = __half22float2(r1);
            float2 f2 = __half22float2(r2);
            float2 f3 = __half22float2(r3);
            accA.x += f0.x; accA.y += f0.y;
            accB.x += f1.x; accB.y += f1.y;
            accC.x += f2.x; accC.y += f2.y;
            accD.x += f3.x; accD.y += f3.y;
        }
        for (; k < end; k++) {                          // tail (<=3 edges)
            int s = __ldg(&g_csr[k]);
            float2 f = __half22float2(__ldg(&T[(size_t)s * 32 + lane]));
            accA.x += f.x; accA.y += f.y;
        }
        float ax = (accA.x + accB.x) + (accC.x + accD.x);
        float ay = (accA.y + accB.y) + (accC.y + accD.y);
        // h = di*a, then BN affine + ReLU  (fold di into scale)
        float o0 = fmaxf(fmaf(ax, di * sc0, sh0), 0.f);
        float o1 = fmaxf(fmaf(ay, di * sc1, sh1), 0.f);
        g_h2[(size_t)i * 32 + lane] = make_float2(o0, o1);
        if (do_pool) {
            int g = __ldg(&batch[i]);
            atomicAdd(&g_psum[g * HF + c0], o0);
            atomicAdd(&g_psum[g * HF + c1], o1);
            atomicMax(&g_pmax[g * HF + c0], __float_as_uint(o0));
            atomicMax(&g_pmax[g * HF + c1], __float_as_uint(o1));
            if (lane == 0) atomicAdd(&g_pcnt[g], 1);
        }
    }
}

// ------------------------------ head -----------------------------------------

__global__ void mlp_kernel(const float* __restrict__ Wc1, const float* __restrict__ bc1,
                           const float* __restrict__ Wc2, const float* __restrict__ bc2,
                           float* __restrict__ out) {
    int lane = threadIdx.x & 31;
    int g = (blockIdx.x * blockDim.x + threadIdx.x) >> 5;
    if (g >= GG) return;
    float inv = 1.0f / fmaxf((float)g_pcnt[g], 1.0f);
    float p0 = g_psum[g * HF + lane]      * inv;
    float p1 = g_psum[g * HF + lane + 32] * inv;
    float p2 = __uint_as_float(g_pmax[g * HF + lane]);
    float p3 = __uint_as_float(g_pmax[g * HF + lane + 32]);
    g_psum[g * HF + lane] = 0.f;  g_psum[g * HF + lane + 32] = 0.f;
    g_pmax[g * HF + lane] = 0u;   g_pmax[g * HF + lane + 32] = 0u;
    if (lane == 0) g_pcnt[g] = 0;

    float h0 = bc1[lane], h1 = bc1[lane + 32];
#pragma unroll
    for (int k = 0; k < 32; k++) {
        float v0 = __shfl_sync(FULL, p0, k);
        float v1 = __shfl_sync(FULL, p1, k);
        float v2 = __shfl_sync(FULL, p2, k);
        float v3 = __shfl_sync(FULL, p3, k);
        h0 = fmaf(v0, Wc1[k * HF + lane], h0);
        h0 = fmaf(v1, Wc1[(k + 32) * HF + lane], h0);
        h0 = fmaf(v2, Wc1[(k + 64) * HF + lane], h0);
        h0 = fmaf(v3, Wc1[(k + 96) * HF + lane], h0);
        h1 = fmaf(v0, Wc1[k * HF + lane + 32], h1);
        h1 = fmaf(v1, Wc1[(k + 32) * HF + lane + 32], h1);
        h1 = fmaf(v2, Wc1[(k + 64) * HF + lane + 32], h1);
        h1 = fmaf(v3, Wc1[(k + 96) * HF + lane + 32], h1);
    }
    h0 = fmaxf(h0, 0.f);
    h1 = fmaxf(h1, 0.f);
    float o0 = h0 * Wc2[lane * 2 + 0] + h1 * Wc2[(lane + 32) * 2 + 0];
    float o1 = h0 * Wc2[lane * 2 + 1] + h1 * Wc2[(lane + 32) * 2 + 1];
#pragma unroll
    for (int off = 16; off; off >>= 1) {
        o0 += __shfl_down_sync(FULL, o0, off);
        o1 += __shfl_down_sync(FULL, o1, off);
    }
    if (lane == 0) {
        out[g * 2 + 0] = o0 + bc2[0];
        out[g * 2 + 1] = o1 + bc2[1];
    }
}

// ------------------------------ launch ---------------------------------------

extern "C" void kernel_launch(void* const* d_in, const int* in_sizes, int n_in,
                              void* d_out, int out_size) {
    const float* x    = (const float*)d_in[0];
    const int*   erow = (const int*)d_in[1];
    const int*   ecol = (const int*)d_in[2];
    const int*   batch= (const int*)d_in[3];
    const float* W0   = (const float*)d_in[4];
    const float* b0   = (const float*)d_in[5];
    const float* W1   = (const float*)d_in[6];
    const float* b1   = (const float*)d_in[7];
    const float* W2   = (const float*)d_in[8];
    const float* b2   = (const float*)d_in[9];
    const float* bng  = (const float*)d_in[10];
    const float* bnb  = (const float*)d_in[11];
    const float* bnm  = (const float*)d_in[12];
    const float* bnv  = (const float*)d_in[13];
    const float* Wc1  = (const float*)d_in[14];
    const float* bc1  = (const float*)d_in[15];
    const float* Wc2  = (const float*)d_in[16];
    const float* bc2  = (const float*)d_in[17];
    float* out = (float*)d_out;

    const int GB = 2048, BT = 256;
    const int GEMM_BLOCKS = (NN + 63) / 64;

    deg_kernel<<<(EE / 4 + 255) / 256, 256>>>(ecol);
    scan1_kernel<<<(NN + 1023) / 1024, 1024>>>();        // computes g_dinv
    scan2_kernel<<<1, 128>>>((NN + 1023) / 1024);
    gemm26_kernel<<<GEMM_BLOCKS, 256>>>(x, W0);          // uses g_dinv (ready)
    scan3_kernel<<<(NN + 255) / 256, 256>>>();
    csr_kernel<<<(EE / 4 + 255) / 256, 256>>>(erow, ecol);

    agg_kernel<<<GB, BT>>>(b0, bng, bnb, bnm, bnv, 0, 0, batch);
    gemm64_kernel<<<GEMM_BLOCKS, 256>>>(W1);
    agg_kernel<<<GB, BT>>>(b1, bng, bnb, bnm, bnv, 1, 0, batch);
    gemm64_kernel<<<GEMM_BLOCKS, 256>>>(W2);
    agg_kernel<<<GB, BT>>>(b2, bng, bnb, bnm, bnv, 2, 1, batch);
    mlp_kernel<<<(GG * 32 + 255) / 256, 256>>>(Wc1, bc1, Wc2, bc2, out);
}

// round 15
// speedup vs baseline: 1.2677x; 1.0002x over previous
#include <cuda_runtime.h>
#include <cuda_fp16.h>

// ---------------------------------------------------------------------------
// GCN: 3x (GEMM -> GCN-normalized aggregate w/ self loops -> BN(eval)+ReLU)
//      -> global mean+max pool per graph -> 2-layer MLP head.
// R12 skeleton (258.6us) + R13 fusion, FIXED: device-global t buffers are now
// selected INSIDE device code (template), never passed from host (R13's bug:
// host-side __device__ symbol address is a shadow, not a device pointer).
// agg(l)+gemm(W_{l+1}) fused per 64-node tile via fp32 smem h tile; global h
// buffer eliminated; final layer = pool-only aggregate.
// ---------------------------------------------------------------------------

#define NN   100000
#define EE   1600000
#define GG   512
#define INF  26
#define HF   64
#define EPSV 1e-5f
#define FULL 0xffffffffu

typedef unsigned long long ull;

// Scratch (device globals; zero-initialized at load, self-cleaned per call)
__device__ __half2  g_thA[(size_t)NN * 32]; // pre-scaled features dinv*t (buf A)
__device__ __half2  g_thB[(size_t)NN * 32]; // pre-scaled features dinv*t (buf B)
__device__ int      g_deg[NN];              // edge-only in-degree (reset by scan1)
__device__ float    g_dinv[NN];             // (deg+1)^{-1/2}
__device__ int      g_rowptr[NN + 1];       // CSR row pointers (by target)
__device__ int      g_cursor[NN];           // fill cursors
__device__ int      g_csr[EE];              // source node per CSR slot
__device__ int      g_bsum[128];            // scan block sums
__device__ float    g_psum[GG * HF];        // pooling: sum   (reset by mlp)
__device__ unsigned g_pmax[GG * HF];        // pooling: max   (reset by mlp)
__device__ int      g_pcnt[GG];             // pooling: count (reset by mlp)

// ---------------------------- f32x2 helpers --------------------------------

__device__ __forceinline__ ull ffma2(ull a, ull b, ull c) {
    ull d;
    asm("fma.rn.f32x2 %0, %1, %2, %3;" : "=l"(d) : "l"(a), "l"(b), "l"(c));
    return d;
}
__device__ __forceinline__ ull pack2(float x, float y) {
    ull d;
    asm("mov.b64 %0, {%1, %2};" : "=l"(d) : "f"(x), "f"(y));
    return d;
}
__device__ __forceinline__ float2 unpack2(ull v) {
    float2 r;
    asm("mov.b64 {%0, %1}, %2;" : "=f"(r.x), "=f"(r.y) : "l"(v));
    return r;
}

// Unweighted gather-sum over pre-scaled fp16 rows (self row + in-edges).
// 4 independent row streams, prefetched 4 ahead. fp32 accumulation.
__device__ __forceinline__ float2 gather_sum(const __half2* __restrict__ T,
                                             int i, int lane) {
    float2 accA = __half22float2(__ldg(&T[(size_t)i * 32 + lane]));  // self
    float2 accB = make_float2(0.f, 0.f);
    float2 accC = make_float2(0.f, 0.f);
    float2 accD = make_float2(0.f, 0.f);
    int k   = __ldg(&g_rowptr[i]);
    int end = __ldg(&g_rowptr[i + 1]);
    if (k + 3 < end) {
        int s0 = __ldg(&g_csr[k]);
        int s1 = __ldg(&g_csr[k + 1]);
        int s2 = __ldg(&g_csr[k + 2]);
        int s3 = __ldg(&g_csr[k + 3]);
        __half2 r0 = __ldg(&T[(size_t)s0 * 32 + lane]);
        __half2 r1 = __ldg(&T[(size_t)s1 * 32 + lane]);
        __half2 r2 = __ldg(&T[(size_t)s2 * 32 + lane]);
        __half2 r3 = __ldg(&T[(size_t)s3 * 32 + lane]);
        k += 4;
        while (k + 3 < end) {
            int n0 = __ldg(&g_csr[k]);
            int n1 = __ldg(&g_csr[k + 1]);
            int n2 = __ldg(&g_csr[k + 2]);
            int n3 = __ldg(&g_csr[k + 3]);
            __half2 q0 = __ldg(&T[(size_t)n0 * 32 + lane]);
            __half2 q1 = __ldg(&T[(size_t)n1 * 32 + lane]);
            __half2 q2 = __ldg(&T[(size_t)n2 * 32 + lane]);
            __half2 q3 = __ldg(&T[(size_t)n3 * 32 + lane]);
            float2 f0 = __half22float2(r0);
            float2 f1 = __half22float2(r1);
            float2 f2 = __half22float2(r2);
            float2 f3 = __half22float2(r3);
            accA.x += f0.x; accA.y += f0.y;
            accB.x += f1.x; accB.y += f1.y;
            accC.x += f2.x; accC.y += f2.y;
            accD.x += f3.x; accD.y += f3.y;
            r0 = q0; r1 = q1; r2 = q2; r3 = q3;
            k += 4;
        }
        float2 f0 = __half22float2(r0);
        float2 f1 = __half22float2(r1);
        float2 f2 = __half22float2(r2);
        float2 f3 = __half22float2(r3);
        accA.x += f0.x; accA.y += f0.y;
        accB.x += f1.x; accB.y += f1.y;
        accC.x += f2.x; accC.y += f2.y;
        accD.x += f3.x; accD.y += f3.y;
    }
    for (; k < end; k++) {                          // tail (<=3 edges)
        int s = __ldg(&g_csr[k]);
        float2 f = __half22float2(__ldg(&T[(size_t)s * 32 + lane]));
        accA.x += f.x; accA.y += f.y;
    }
    return make_float2((accA.x + accB.x) + (accC.x + accD.x),
                       (accA.y + accB.y) + (accC.y + accD.y));
}

// --------------------------- setup kernels ---------------------------------

__global__ void deg_kernel(const int* __restrict__ ecol) {
    int base = (blockIdx.x * blockDim.x + threadIdx.x) * 4;
    if (base + 3 < EE) {
        int4 c = *(const int4*)(ecol + base);
        atomicAdd(&g_deg[c.x], 1);
        atomicAdd(&g_deg[c.y], 1);
        atomicAdd(&g_deg[c.z], 1);
        atomicAdd(&g_deg[c.w], 1);
    } else {
        for (int e = base; e < EE; e++) atomicAdd(&g_deg[ecol[e]], 1);
    }
}

__global__ void scan1_kernel() {
    __shared__ int sbuf[1024];
    int t = threadIdx.x;
    int idx = blockIdx.x * 1024 + t;
    int v = 0;
    if (idx < NN) {
        v = g_deg[idx];                         // edges only
        g_deg[idx] = 0;                         // self-clean for next call
        g_dinv[idx] = rsqrtf((float)(v + 1));   // +1 self loop
    }
    sbuf[t] = v;
    __syncthreads();
    for (int off = 1; off < 1024; off <<= 1) {
        int tmp = (t >= off) ? sbuf[t - off] : 0;
        __syncthreads();
        sbuf[t] += tmp;
        __syncthreads();
    }
    if (idx < NN) g_rowptr[idx] = sbuf[t] - v;
    if (t == 1023) g_bsum[blockIdx.x] = sbuf[1023];
}

__global__ void scan2_kernel(int nb) {
    __shared__ int sb[128];
    int t = threadIdx.x;
    int v = (t < nb) ? g_bsum[t] : 0;
    sb[t] = v;
    __syncthreads();
    for (int off = 1; off < 128; off <<= 1) {
        int tmp = (t >= off) ? sb[t - off] : 0;
        __syncthreads();
        sb[t] += tmp;
        __syncthreads();
    }
    if (t < nb) g_bsum[t] = sb[t] - v;
}

__global__ void scan3_kernel() {
    int idx = blockIdx.x * blockDim.x + threadIdx.x;
    if (idx < NN) {
        int rp = g_rowptr[idx] + g_bsum[idx >> 10];
        g_rowptr[idx] = rp;
        g_cursor[idx] = rp;
    }
    if (idx == 0) g_rowptr[NN] = EE;
}

__global__ void csr_kernel(const int* __restrict__ erow, const int* __restrict__ ecol) {
    int base = (blockIdx.x * blockDim.x + threadIdx.x) * 4;
    if (base + 3 < EE) {
        int4 r = *(const int4*)(erow + base);
        int4 c = *(const int4*)(ecol + base);
        g_csr[atomicAdd(&g_cursor[c.x], 1)] = r.x;
        g_csr[atomicAdd(&g_cursor[c.y], 1)] = r.y;
        g_csr[atomicAdd(&g_cursor[c.z], 1)] = r.z;
        g_csr[atomicAdd(&g_cursor[c.w], 1)] = r.w;
    } else {
        for (int e = base; e < EE; e++)
            g_csr[atomicAdd(&g_cursor[ecol[e]], 1)] = erow[e];
    }
}

// --------------------------- layer-0 GEMM -----------------------------------
// Warp-per-8-nodes, k-split FFMA2; epilogue scales by dinv and stores
// pre-scaled half2 rows into g_thA (referenced in device code only).
__global__ __launch_bounds__(256) void gemm26_kernel(const float* __restrict__ x,
                                                     const float* __restrict__ W) {
    __shared__ __align__(16) ull  Wp[14 * HF];
    __shared__ __align__(16) float xsf[64 * 28];
    int tid = threadIdx.x;
    for (int i = tid; i < 14 * HF; i += 256) {
        int k2 = i >> 6, c = i & 63;
        float w0 = (2 * k2     < INF) ? W[(2 * k2)     * HF + c] : 0.f;
        float w1 = (2 * k2 + 1 < INF) ? W[(2 * k2 + 1) * HF + c] : 0.f;
        Wp[i] = pack2(w0, w1);
    }
    int base = blockIdx.x * 64;
    int cnt = min(64, NN - base);
    for (int i = tid; i < cnt * 28; i += 256) {
        int row = i / 28, col = i - row * 28;
        xsf[i] = (col < INF) ? __ldg(&x[(size_t)(base + row) * INF + col]) : 0.f;
    }
    __syncthreads();

    int lane = tid & 31;
    int n0 = (tid >> 5) * 8;
    if (n0 >= cnt) return;
    const longlong2* X4 = (const longlong2*)xsf;
    const longlong2* Wq = (const longlong2*)Wp;

    ull a0[8], a1[8];
#pragma unroll
    for (int n = 0; n < 8; n++) { a0[n] = 0ull; a1[n] = 0ull; }
#pragma unroll
    for (int k4 = 0; k4 < 7; k4++) {
        longlong2 wq0 = Wq[(2 * k4) * 32 + lane];
        longlong2 wq1 = Wq[(2 * k4 + 1) * 32 + lane];
#pragma unroll
        for (int n = 0; n < 8; n++) {
            longlong2 xq = X4[(n0 + n) * 7 + k4];
            a0[n] = ffma2((ull)xq.x, (ull)wq0.x, a0[n]);
            a1[n] = ffma2((ull)xq.x, (ull)wq0.y, a1[n]);
            a0[n] = ffma2((ull)xq.y, (ull)wq1.x, a0[n]);
            a1[n] = ffma2((ull)xq.y, (ull)wq1.y, a1[n]);
        }
    }
#pragma unroll
    for (int n = 0; n < 8; n++) {
        int node = base + n0 + n;
        if (node < NN) {
            float dn = __ldg(&g_dinv[node]);
            float2 v0 = unpack2(a0[n]);
            float2 v1 = unpack2(a1[n]);
            g_thA[(size_t)node * 32 + lane] =
                __floats2half2_rn(dn * (v0.x + v0.y), dn * (v1.x + v1.y));
        }
    }
}

// ------------------------ fused aggregate + GEMM -----------------------------
// Block = 64 nodes. Phase 1: warp-per-node gather from tin + BN/ReLU ->
// fp32 smem tile. Phase 2: FFMA2 gemm with W (next layer) from smem;
// epilogue writes pre-scaled fp16 rows to tout.
// SRCB=0: tin=g_thA, tout=g_thB.  SRCB=1: tin=g_thB, tout=g_thA.
template <int SRCB>
__global__ __launch_bounds__(256) void aggmm_kernel(
        const float* __restrict__ W,        // next-layer weight [64,64]
        const float* __restrict__ bias,     // this layer bias
        const float* __restrict__ bng, const float* __restrict__ bnb,
        const float* __restrict__ bnm, const float* __restrict__ bnv,
        int layer) {
    const __half2* __restrict__ tin = SRCB ? g_thB : g_thA;
    __half2* __restrict__ tout      = SRCB ? g_thA : g_thB;

    __shared__ __align__(16) ull    Wp[32 * HF];   // 16 KB
    __shared__ __align__(16) float2 hs[64 * 32];   // 16 KB fp32 h tile
    int tid = threadIdx.x;
    for (int i = tid; i < 32 * HF; i += 256) {
        int k2 = i >> 6, c = i & 63;
        Wp[i] = pack2(W[(2 * k2) * HF + c], W[(2 * k2 + 1) * HF + c]);
    }
    int base = blockIdx.x * 64;
    int cnt = min(64, NN - base);
    int lane = tid & 31;
    int warp = tid >> 5;
    int c0 = 2 * lane, c1 = c0 + 1;
    int o = layer * HF;
    float sc0 = bng[o + c0] * rsqrtf(bnv[o + c0] + EPSV);
    float sc1 = bng[o + c1] * rsqrtf(bnv[o + c1] + EPSV);
    float sh0 = (bias[c0] - bnm[o + c0]) * sc0 + bnb[o + c0];
    float sh1 = (bias[c1] - bnm[o + c1]) * sc1 + bnb[o + c1];

    // Phase 1: aggregate 8 nodes per warp into smem
    int nend = min(warp * 8 + 8, cnt);
    for (int n = warp * 8; n < nend; n++) {
        int i = base + n;
        float di = __ldg(&g_dinv[i]);
        float2 a = gather_sum(tin, i, lane);
        float o0 = fmaxf(fmaf(a.x, di * sc0, sh0), 0.f);
        float o1 = fmaxf(fmaf(a.y, di * sc1, sh1), 0.f);
        hs[n * 32 + lane] = make_float2(o0, o1);
    }
    __syncthreads();

    // Phase 2: gemm from smem tile
    int n0 = warp * 8;
    if (n0 >= cnt) return;
    const longlong2* X4 = (const longlong2*)hs;
    const longlong2* Wq = (const longlong2*)Wp;
    ull a0[8], a1[8];
#pragma unroll
    for (int n = 0; n < 8; n++) { a0[n] = 0ull; a1[n] = 0ull; }
#pragma unroll
    for (int k4 = 0; k4 < 16; k4++) {
        longlong2 wq0 = Wq[(2 * k4) * 32 + lane];
        longlong2 wq1 = Wq[(2 * k4 + 1) * 32 + lane];
#pragma unroll
        for (int n = 0; n < 8; n++) {
            longlong2 xq = X4[(n0 + n) * 16 + k4];
            a0[n] = ffma2((ull)xq.x, (ull)wq0.x, a0[n]);
            a1[n] = ffma2((ull)xq.x, (ull)wq0.y, a1[n]);
            a0[n] = ffma2((ull)xq.y, (ull)wq1.x, a0[n]);
            a1[n] = ffma2((ull)xq.y, (ull)wq1.y, a1[n]);
        }
    }
#pragma unroll
    for (int n = 0; n < 8; n++) {
        int node = base + n0 + n;
        if (node < NN) {
            float dn = __ldg(&g_dinv[node]);
            float2 v0 = unpack2(a0[n]);
            float2 v1 = unpack2(a1[n]);
            tout[(size_t)node * 32 + lane] =
                __floats2half2_rn(dn * (v0.x + v0.y), dn * (v1.x + v1.y));
        }
    }
}

// ------------------------ final aggregate + pooling ---------------------------
// Warp per node (grid-strided); gathers from g_thA, BN/ReLU, pooling only.
__global__ __launch_bounds__(256) void aggpool_kernel(
        const float* __restrict__ bias,
        const float* __restrict__ bng, const float* __restrict__ bnb,
        const float* __restrict__ bnm, const float* __restrict__ bnv,
        int layer, const int* __restrict__ batch) {
    int lane = threadIdx.x & 31;
    int warp = (blockIdx.x * blockDim.x + threadIdx.x) >> 5;
    int nw   = (gridDim.x * blockDim.x) >> 5;
    int c0 = 2 * lane, c1 = c0 + 1;
    int o = layer * HF;
    float sc0 = bng[o + c0] * rsqrtf(bnv[o + c0] + EPSV);
    float sc1 = bng[o + c1] * rsqrtf(bnv[o + c1] + EPSV);
    float sh0 = (bias[c0] - bnm[o + c0]) * sc0 + bnb[o + c0];
    float sh1 = (bias[c1] - bnm[o + c1]) * sc1 + bnb[o + c1];

    for (int i = warp; i < NN; i += nw) {
        float di = __ldg(&g_dinv[i]);
        float2 a = gather_sum(g_thA, i, lane);
        float o0 = fmaxf(fmaf(a.x, di * sc0, sh0), 0.f);
        float o1 = fmaxf(fmaf(a.y, di * sc1, sh1), 0.f);
        int g = __ldg(&batch[i]);
        atomicAdd(&g_psum[g * HF + c0], o0);
        atomicAdd(&g_psum[g * HF + c1], o1);
        atomicMax(&g_pmax[g * HF + c0], __float_as_uint(o0));
        atomicMax(&g_pmax[g * HF + c1], __float_as_uint(o1));
        if (lane == 0) atomicAdd(&g_pcnt[g], 1);
    }
}

// ------------------------------ head -----------------------------------------

__global__ void mlp_kernel(const float* __restrict__ Wc1, const float* __restrict__ bc1,
                           const float* __restrict__ Wc2, const float* __restrict__ bc2,
                           float* __restrict__ out) {
    int lane = threadIdx.x & 31;
    int g = (blockIdx.x * blockDim.x + threadIdx.x) >> 5;
    if (g >= GG) return;
    float inv = 1.0f / fmaxf((float)g_pcnt[g], 1.0f);
    float p0 = g_psum[g * HF + lane]      * inv;
    float p1 = g_psum[g * HF + lane + 32] * inv;
    float p2 = __uint_as_float(g_pmax[g * HF + lane]);
    float p3 = __uint_as_float(g_pmax[g * HF + lane + 32]);
    g_psum[g * HF + lane] = 0.f;  g_psum[g * HF + lane + 32] = 0.f;
    g_pmax[g * HF + lane] = 0u;   g_pmax[g * HF + lane + 32] = 0u;
    if (lane == 0) g_pcnt[g] = 0;

    float h0 = bc1[lane], h1 = bc1[lane + 32];
#pragma unroll
    for (int k = 0; k < 32; k++) {
        float v0 = __shfl_sync(FULL, p0, k);
        float v1 = __shfl_sync(FULL, p1, k);
        float v2 = __shfl_sync(FULL, p2, k);
        float v3 = __shfl_sync(FULL, p3, k);
        h0 = fmaf(v0, Wc1[k * HF + lane], h0);
        h0 = fmaf(v1, Wc1[(k + 32) * HF + lane], h0);
        h0 = fmaf(v2, Wc1[(k + 64) * HF + lane], h0);
        h0 = fmaf(v3, Wc1[(k + 96) * HF + lane], h0);
        h1 = fmaf(v0, Wc1[k * HF + lane + 32], h1);
        h1 = fmaf(v1, Wc1[(k + 32) * HF + lane + 32], h1);
        h1 = fmaf(v2, Wc1[(k + 64) * HF + lane + 32], h1);
        h1 = fmaf(v3, Wc1[(k + 96) * HF + lane + 32], h1);
    }
    h0 = fmaxf(h0, 0.f);
    h1 = fmaxf(h1, 0.f);
    float o0 = h0 * Wc2[lane * 2 + 0] + h1 * Wc2[(lane + 32) * 2 + 0];
    float o1 = h0 * Wc2[lane * 2 + 1] + h1 * Wc2[(lane + 32) * 2 + 1];
#pragma unroll
    for (int off = 16; off; off >>= 1) {
        o0 += __shfl_down_sync(FULL, o0, off);
        o1 += __shfl_down_sync(FULL, o1, off);
    }
    if (lane == 0) {
        out[g * 2 + 0] = o0 + bc2[0];
        out[g * 2 + 1] = o1 + bc2[1];
    }
}

// ------------------------------ launch ---------------------------------------

extern "C" void kernel_launch(void* const* d_in, const int* in_sizes, int n_in,
                              void* d_out, int out_size) {
    const float* x    = (const float*)d_in[0];
    const int*   erow = (const int*)d_in[1];
    const int*   ecol = (const int*)d_in[2];
    const int*   batch= (const int*)d_in[3];
    const float* W0   = (const float*)d_in[4];
    const float* b0   = (const float*)d_in[5];
    const float* W1   = (const float*)d_in[6];
    const float* b1   = (const float*)d_in[7];
    const float* W2   = (const float*)d_in[8];
    const float* b2   = (const float*)d_in[9];
    const float* bng  = (const float*)d_in[10];
    const float* bnb  = (const float*)d_in[11];
    const float* bnm  = (const float*)d_in[12];
    const float* bnv  = (const float*)d_in[13];
    const float* Wc1  = (const float*)d_in[14];
    const float* bc1  = (const float*)d_in[15];
    const float* Wc2  = (const float*)d_in[16];
    const float* bc2  = (const float*)d_in[17];
    float* out = (float*)d_out;

    const int GB = 2048, BT = 256;
    const int TILE_BLOCKS = (NN + 63) / 64;

    deg_kernel<<<(EE / 4 + 255) / 256, 256>>>(ecol);
    scan1_kernel<<<(NN + 1023) / 1024, 1024>>>();        // computes g_dinv
    scan2_kernel<<<1, 128>>>((NN + 1023) / 1024);
    gemm26_kernel<<<TILE_BLOCKS, 256>>>(x, W0);          // x,W0 -> thA
    scan3_kernel<<<(NN + 255) / 256, 256>>>();
    csr_kernel<<<(EE / 4 + 255) / 256, 256>>>(erow, ecol);

    // fused layers: agg(l) + gemm(W_{l+1})   (thA -> thB -> thA)
    aggmm_kernel<0><<<TILE_BLOCKS, 256>>>(W1, b0, bng, bnb, bnm, bnv, 0);
    aggmm_kernel<1><<<TILE_BLOCKS, 256>>>(W2, b1, bng, bnb, bnm, bnv, 1);
    // final layer: aggregate + pooling only (reads thA)
    aggpool_kernel<<<GB, BT>>>(b2, bng, bnb, bnm, bnv, 2, batch);
    mlp_kernel<<<(GG * 32 + 255) / 256, 256>>>(Wc1, bc1, Wc2, bc2, out);
}